// round 17
// baseline (speedup 1.0000x reference)
#include <cuda_runtime.h>
#include <cuda_bf16.h>
#include <math.h>

#define BDIM 512
#define DDIM 512
#define CDIM 100000
#define SCALE_F 64.0f
#define MARGIN_F 0.35f

#define TILE_N 192                      // 6 warp-cols x 32
#define NT 521                          // ceil(100000/192); 521*192=100032
#define C_PAD (NT * TILE_N)             // 100032 (multiple of 8)
#define NPART (NT * 6)                  // per-row partials: 6 warp-cols
#define GRIDX 37                        // 37*4 = 148 CTAs = 1 wave
#define NB_TILE 24                      // n8-blocks per tile (192/8)

#define ASTRIDE_B 1040                  // A smem row stride (512*2 + 16)
#define SMEM_DYN (128 * ASTRIDE_B)      // 133120 (A only!)

// ---------------- device scratch ----------------
__device__ __nv_bfloat16 g_xb[BDIM * DDIM];
__device__ float         g_xn[BDIM * DDIM];
__device__ unsigned char g_wp[(size_t)C_PAD * 1024];  // fragment-permuted bf16 W
__device__ float         g_rss[C_PAD];                // exact fp32 ||w||^2
__device__ float         g_pm[(size_t)BDIM * NPART];
__device__ float         g_ps[(size_t)BDIM * NPART];
__device__ float         g_cosgt[BDIM];
__device__ float         g_nll[BDIM];
__device__ int           g_is64;

// ---------------- helpers ----------------
__device__ __forceinline__ unsigned smem_u32(const void* p) {
    unsigned a;
    asm("{ .reg .u64 t; cvta.to.shared.u64 t, %1; cvt.u32.u64 %0, t; }" : "=r"(a) : "l"(p));
    return a;
}
__device__ __forceinline__ unsigned pack_bf16x2(float a, float b) {
    __nv_bfloat162 t = __floats2bfloat162_rn(a, b);
    return *(unsigned*)&t;
}

// ---------------- small kernels ----------------
__global__ void detect_gt_kernel(const int* __restrict__ graw) {
    __shared__ int any_nz;
    if (threadIdx.x == 0) any_nz = 0;
    __syncthreads();
    if ((threadIdx.x & 1) && graw[threadIdx.x] != 0) any_nz = 1;
    __syncthreads();
    if (threadIdx.x == 0) g_is64 = any_nz ? 0 : 1;
}

__global__ void __launch_bounds__(128) norm_x_kernel(const float* __restrict__ x) {
    int b = blockIdx.x, tid = threadIdx.x;
    float4 v = ((const float4*)(x + (size_t)b * DDIM))[tid];
    float ss = v.x*v.x + v.y*v.y + v.z*v.z + v.w*v.w;
    #pragma unroll
    for (int o = 16; o; o >>= 1) ss += __shfl_xor_sync(0xffffffffu, ss, o);
    __shared__ float sm[4];
    if ((tid & 31) == 0) sm[tid >> 5] = ss;
    __syncthreads();
    float tot = sm[0] + sm[1] + sm[2] + sm[3];
    float r = 1.0f / fmaxf(sqrtf(tot), 1e-12f);
    float4 n = make_float4(v.x*r, v.y*r, v.z*r, v.w*r);
    ((float4*)(g_xn + (size_t)b * DDIM))[tid] = n;
    __nv_bfloat162* dst = (__nv_bfloat162*)(g_xb + (size_t)b * DDIM);
    dst[tid * 2 + 0] = __floats2bfloat162_rn(n.x, n.y);
    dst[tid * 2 + 1] = __floats2bfloat162_rn(n.z, n.w);
}

// W fp32 -> fragment-permuted bf16 + exact row ||w||^2.
// Block (nb, kb): 256B at ((nb*32)+kb)*256. Lane slot l = (c&7)*4 + ((k&7)>>1):
// 8B = {B[c][kb*16 + p*2], +1, B[c][kb*16+8+p*2], +1}  (p = l&3)
__global__ void __launch_bounds__(128) cvt_w_kernel(const float* __restrict__ wt) {
    int c = blockIdx.x * 4 + (threadIdx.x >> 5);
    int lane = threadIdx.x & 31;            // = kb (k16 block)
    float f[16];
    float ss = 0.0f;
    if (c < CDIM) {
        const float4* src = (const float4*)(wt + (size_t)c * DDIM + lane * 16);
        #pragma unroll
        for (int q = 0; q < 4; q++) {
            float4 v = src[q];
            f[q*4+0] = v.x; f[q*4+1] = v.y; f[q*4+2] = v.z; f[q*4+3] = v.w;
            ss += v.x*v.x + v.y*v.y + v.z*v.z + v.w*v.w;
        }
    } else {
        #pragma unroll
        for (int q = 0; q < 16; q++) f[q] = 0.0f;
    }
    #pragma unroll
    for (int o = 16; o; o >>= 1) ss += __shfl_xor_sync(0xffffffffu, ss, o);
    if (lane == 0) g_rss[c] = (c < CDIM) ? ss : 0.0f;

    unsigned u[8];
    #pragma unroll
    for (int p = 0; p < 4; p++) {
        u[p*2+0] = pack_bf16x2(f[p*2],     f[p*2+1]);
        u[p*2+1] = pack_bf16x2(f[8+p*2],   f[8+p*2+1]);
    }
    unsigned char* dst = g_wp + ((size_t)(c >> 3) * 32 + lane) * 256 + (c & 7) * 32;
    ((uint4*)dst)[0] = make_uint4(u[0], u[1], u[2], u[3]);
    ((uint4*)dst)[1] = make_uint4(u[4], u[5], u[6], u[7]);
}

__global__ void __launch_bounds__(128) cosgt_kernel(const void* __restrict__ gt,
                                                    const float* __restrict__ wt) {
    int b = blockIdx.x, tid = threadIdx.x;
    long long c = g_is64 ? ((const long long*)gt)[b] : (long long)((const int*)gt)[b];
    float4 w  = ((const float4*)(wt + (size_t)c * DDIM))[tid];
    float4 xn = ((const float4*)(g_xn + (size_t)b * DDIM))[tid];
    float ss = w.x*w.x + w.y*w.y + w.z*w.z + w.w*w.w;
    float dp = w.x*xn.x + w.y*xn.y + w.z*xn.z + w.w*xn.w;
    #pragma unroll
    for (int o = 16; o; o >>= 1) {
        ss += __shfl_xor_sync(0xffffffffu, ss, o);
        dp += __shfl_xor_sync(0xffffffffu, dp, o);
    }
    __shared__ float sms[4], smd[4];
    if ((tid & 31) == 0) { sms[tid >> 5] = ss; smd[tid >> 5] = dp; }
    __syncthreads();
    if (tid == 0) {
        float tss = sms[0] + sms[1] + sms[2] + sms[3];
        float tdp = smd[0] + smd[1] + smd[2] + smd[3];
        g_cosgt[b] = tdp / fmaxf(sqrtf(tss), 1e-12f);
    }
}

// ---------------- barrier-free GEMM: B fragments direct from GMEM ----------------
// grid (37, 4), 384 threads = 12 independent warps (2m x 6n), warp tile 64x32.
// A [128x512] bf16 in SMEM (staged once); B via 16 LDG.64/warp/chunk, reg
// double-buffered. No mainloop synchronization of any kind.
__global__ void __launch_bounds__(384, 1) gemm_softmax_kernel() {
    extern __shared__ char smem[];
    unsigned sbA = smem_u32(smem);

    int tid  = threadIdx.x;
    int lane = tid & 31;
    int warp = tid >> 5;
    int wm = warp / 6;        // 0..1
    int wn = warp % 6;        // 0..5
    int m0 = blockIdx.y * 128;
    int bx = blockIdx.x;

    const unsigned char* wp = g_wp;
    int ntiles = (NT - bx + GRIDX - 1) / GRIDX;
    int NC = ntiles * 8;

    // ---- stage A[128x512] bf16 (all 384 threads) ----
    for (int idx = tid; idx < 128 * 64; idx += 384) {
        int r = idx >> 6, s = idx & 63;
        uint4 v = *(const uint4*)(g_xb + (size_t)(m0 + r) * DDIM + s * 8);
        *(uint4*)(smem + r * ASTRIDE_B + s * 16) = v;
    }
    __syncthreads();   // only block-wide sync in the kernel

    uint2 b[2][4][4];  // [parity][j n8-tile][k16]

    // load B fragments for global chunk c into parity c&1
    auto LOADB = [&](int c) {
        int ts = c >> 3, ck = c & 7;
        int nb0 = (bx + ts * GRIDX) * NB_TILE + wn * 4;
        const unsigned char* p = wp + ((size_t)nb0 * 32 + ck * 4) * 256 + lane * 8;
        int par = c & 1;
        #pragma unroll
        for (int j = 0; j < 4; j++)
            #pragma unroll
            for (int k = 0; k < 4; k++)
                b[par][j][k] = *(const uint2*)(p + j * 8192 + k * 256);
    };

    LOADB(0);

    int g4 = lane >> 2, t4 = lane & 3;
    int aColOff = (lane >> 4) << 3;

    float acc[4][4][4];
    #pragma unroll 1
    for (int c = 0; c < NC; c++) {
        int ck = c & 7;
        if (ck == 0) {
            #pragma unroll
            for (int i = 0; i < 4; i++)
                #pragma unroll
                for (int j = 0; j < 4; j++)
                    #pragma unroll
                    for (int e = 0; e < 4; e++) acc[i][j][e] = 0.0f;
        }
        if (c + 1 < NC) LOADB(c + 1);   // latency hides under MMA below
        int par = c & 1;

        #pragma unroll
        for (int k16 = 0; k16 < 4; k16++) {
            unsigned a[4][4];
            #pragma unroll
            for (int i = 0; i < 4; i++) {
                int r   = wm * 64 + i * 16 + (lane & 15);
                int col = ck * 64 + k16 * 16 + aColOff;
                unsigned addr = sbA + r * ASTRIDE_B + col * 2;
                asm volatile("ldmatrix.sync.aligned.m8n8.x4.shared.b16 {%0,%1,%2,%3}, [%4];"
                             : "=r"(a[i][0]), "=r"(a[i][1]), "=r"(a[i][2]), "=r"(a[i][3])
                             : "r"(addr));
            }
            #pragma unroll
            for (int i = 0; i < 4; i++)
                #pragma unroll
                for (int j = 0; j < 4; j++)
                    asm volatile(
                        "mma.sync.aligned.m16n8k16.row.col.f32.bf16.bf16.f32 "
                        "{%0,%1,%2,%3},{%4,%5,%6,%7},{%8,%9},{%0,%1,%2,%3};"
                        : "+f"(acc[i][j][0]), "+f"(acc[i][j][1]),
                          "+f"(acc[i][j][2]), "+f"(acc[i][j][3])
                        : "r"(a[i][0]), "r"(a[i][1]), "r"(a[i][2]), "r"(a[i][3]),
                          "r"(b[par][j][k16].x), "r"(b[par][j][k16].y));
        }

        if (ck == 7) {
            // ---- per-warp epilogue for tile tp ----
            int tp = c >> 3;
            int nt = bx + tp * GRIDX;
            int n0 = nt * TILE_N + wn * 32;
            float rn[8];
            #pragma unroll
            for (int j = 0; j < 4; j++)
                #pragma unroll
                for (int e2 = 0; e2 < 2; e2++) {
                    int tc = n0 + j * 8 + t4 * 2 + e2;
                    rn[j * 2 + e2] = rsqrtf(fmaxf(g_rss[tc], 1e-30f)) * SCALE_F;
                }
            #pragma unroll
            for (int i = 0; i < 4; i++) {
                #pragma unroll
                for (int h = 0; h < 2; h++) {
                    float m = -INFINITY;
                    #pragma unroll
                    for (int j = 0; j < 4; j++)
                        #pragma unroll
                        for (int e2 = 0; e2 < 2; e2++) {
                            int gc = n0 + j * 8 + t4 * 2 + e2;
                            if (gc < CDIM)
                                m = fmaxf(m, rn[j * 2 + e2] * acc[i][j][h * 2 + e2]);
                        }
                    m = fmaxf(m, __shfl_xor_sync(0xffffffffu, m, 1));
                    m = fmaxf(m, __shfl_xor_sync(0xffffffffu, m, 2));
                    float s = 0.0f;
                    if (m > -1e37f) {
                        #pragma unroll
                        for (int j = 0; j < 4; j++)
                            #pragma unroll
                            for (int e2 = 0; e2 < 2; e2++) {
                                int gc = n0 + j * 8 + t4 * 2 + e2;
                                if (gc < CDIM)
                                    s += __expf(rn[j * 2 + e2] * acc[i][j][h * 2 + e2] - m);
                            }
                    }
                    s += __shfl_xor_sync(0xffffffffu, s, 1);
                    s += __shfl_xor_sync(0xffffffffu, s, 2);
                    if (t4 == 0) {
                        int r = m0 + wm * 64 + i * 16 + h * 8 + g4;
                        size_t idx = (size_t)r * NPART + nt * 6 + wn;
                        g_pm[idx] = fmaxf(m, -3.0e38f);
                        g_ps[idx] = s;
                    }
                }
            }
        }
    }
}

// ---------------- logsumexp merge + margin + NLL ----------------
__global__ void __launch_bounds__(256) reduce_kernel() {
    int b = blockIdx.x, tid = threadIdx.x;
    float M = -INFINITY, S = 0.0f;
    for (int i = tid; i < NPART; i += 256) {
        float m = g_pm[(size_t)b * NPART + i];
        float s = g_ps[(size_t)b * NPART + i];
        if (m > M) { S = S * __expf(M - m) + s; M = m; }
        else       { S += s * __expf(m - M); }
    }
    __shared__ float sm[256], ss[256];
    sm[tid] = M; ss[tid] = S;
    __syncthreads();
    for (int o = 128; o; o >>= 1) {
        if (tid < o) {
            float m2 = sm[tid + o], s2 = ss[tid + o];
            float m1 = sm[tid],     s1 = ss[tid];
            float mn = fmaxf(m1, m2);
            sm[tid] = mn;
            ss[tid] = s1 * __expf(m1 - mn) + s2 * __expf(m2 - mn);
        }
        __syncthreads();
    }
    if (tid == 0) {
        float Mf = sm[0], Sf = ss[0];
        float zg = SCALE_F * g_cosgt[b];
        float zm = zg - SCALE_F * MARGIN_F;
        Sf = Sf - expf(zg - Mf) + expf(zm - Mf);
        float lse = Mf + logf(Sf);
        g_nll[b] = lse - zm;
    }
}

__global__ void __launch_bounds__(512) mean_kernel(float* __restrict__ out) {
    __shared__ float sm[512];
    int t = threadIdx.x;
    sm[t] = g_nll[t];
    __syncthreads();
    for (int o = 256; o; o >>= 1) {
        if (t < o) sm[t] += sm[t + o];
        __syncthreads();
    }
    if (t == 0) out[0] = sm[0] * (1.0f / (float)BDIM);
}

// ---------------- launch ----------------
extern "C" void kernel_launch(void* const* d_in, const int* in_sizes, int n_in,
                              void* d_out, int out_size) {
    const float* x  = (const float*)d_in[0];
    const void*  gt = d_in[1];
    const float* wt = (const float*)d_in[2];
    float* out = (float*)d_out;

    static int smem_set = 0;
    if (!smem_set) {
        cudaFuncSetAttribute(gemm_softmax_kernel,
                             cudaFuncAttributeMaxDynamicSharedMemorySize, SMEM_DYN);
        smem_set = 1;
    }

    detect_gt_kernel<<<1, 512>>>((const int*)gt);
    norm_x_kernel<<<BDIM, 128>>>(x);
    cvt_w_kernel<<<C_PAD / 4, 128>>>(wt);
    cosgt_kernel<<<BDIM, 128>>>(gt, wt);
    gemm_softmax_kernel<<<dim3(GRIDX, 4), 384, SMEM_DYN>>>();
    reduce_kernel<<<BDIM, 256>>>();
    mean_kernel<<<1, 512>>>(out);
}